// round 1
// baseline (speedup 1.0000x reference)
#include <cuda_runtime.h>
#include <math.h>

// Problem constants
#define T_SEQ 2048
#define BATCH 2
#define DMODEL 1024
#define HEADS 16
#define NWAVE 64
#define HDIM 64
#define ROWS (BATCH * T_SEQ)            // 4096
#define SLICE ((size_t)ROWS * DMODEL)   // 4194304 elements
#define BH (BATCH * HEADS)              // 32
#define CHUNK 64
#define NCHUNK (T_SEQ / CHUNK)          // 32

// ---------------- device scratch (no allocations allowed) ----------------
__device__ float g_wave[4 * SLICE];              // qf, kf, qp, kp raw projections
__device__ float g_v[SLICE];                     // v projection [b,t,h*64+d]
__device__ float g_qn[(size_t)BH * T_SEQ * NWAVE];  // normalized q waves [bh][t][w]
__device__ float g_kn[(size_t)BH * T_SEQ * NWAVE];  // normalized k waves [bh][t][w]
__device__ float g_M[(size_t)BH * NCHUNK * NWAVE * HDIM];  // per-chunk kn^T v
__device__ float g_S[(size_t)BH * NCHUNK * NWAVE * HDIM];  // exclusive prefix states
__device__ float g_ao[SLICE];                    // attention output [b,t,h*64+d]

// ---------------- 128x128x8 register-tiled SGEMM (C = A*B + bias) ----------------
// A [M,K] row-major, B [K,N] row-major. 256 threads, 8x8 per thread.
__device__ __forceinline__ void sgemm128(const float* __restrict__ A,
                                         const float* __restrict__ Bw,
                                         const float* __restrict__ bias,
                                         float* __restrict__ C,
                                         int N, int K)
{
    __shared__ float As[8][128];   // transposed A tile: As[k][m]
    __shared__ float Bs[8][128];   // Bs[k][n]
    const int tid  = threadIdx.x;
    const int row0 = blockIdx.y * 128;
    const int col0 = blockIdx.x * 128;
    const int arow = tid >> 1, acol = (tid & 1) * 4;
    const int brow = tid >> 5, bcol = (tid & 31) * 4;
    const int ty = tid >> 4, tx = tid & 15;

    float acc[8][8];
#pragma unroll
    for (int i = 0; i < 8; i++)
#pragma unroll
        for (int j = 0; j < 8; j++) acc[i][j] = 0.f;

    for (int kk = 0; kk < K; kk += 8) {
        float4 a = *(const float4*)(A + (size_t)(row0 + arow) * K + kk + acol);
        As[acol + 0][arow] = a.x;
        As[acol + 1][arow] = a.y;
        As[acol + 2][arow] = a.z;
        As[acol + 3][arow] = a.w;
        float4 b = *(const float4*)(Bw + (size_t)(kk + brow) * N + col0 + bcol);
        *(float4*)(&Bs[brow][bcol]) = b;
        __syncthreads();
#pragma unroll
        for (int k = 0; k < 8; k++) {
            float ar[8], br[8];
#pragma unroll
            for (int i = 0; i < 8; i++) ar[i] = As[k][ty * 8 + i];
#pragma unroll
            for (int j = 0; j < 8; j++) br[j] = Bs[k][tx * 8 + j];
#pragma unroll
            for (int i = 0; i < 8; i++)
#pragma unroll
                for (int j = 0; j < 8; j++)
                    acc[i][j] = fmaf(ar[i], br[j], acc[i][j]);
        }
        __syncthreads();
    }
#pragma unroll
    for (int i = 0; i < 8; i++) {
        int r = row0 + ty * 8 + i;
#pragma unroll
        for (int j = 0; j < 8; j += 4) {
            int c = col0 + tx * 8 + j;
            float4 o;
            o.x = acc[i][j + 0] + bias[c + 0];
            o.y = acc[i][j + 1] + bias[c + 1];
            o.z = acc[i][j + 2] + bias[c + 2];
            o.w = acc[i][j + 3] + bias[c + 3];
            *(float4*)(C + (size_t)r * N + c) = o;
        }
    }
}

// ---------------- projection kernel: 5 GEMMs via blockIdx.z ----------------
__global__ __launch_bounds__(256) void proj_kernel(
    const float* __restrict__ x,
    const float* __restrict__ Wqf, const float* __restrict__ bqf,
    const float* __restrict__ Wkf, const float* __restrict__ bkf,
    const float* __restrict__ Wqp, const float* __restrict__ bqp,
    const float* __restrict__ Wkp, const float* __restrict__ bkp,
    const float* __restrict__ Wv,  const float* __restrict__ bv)
{
    const float* W;
    const float* b;
    float* C;
    switch (blockIdx.z) {
        case 0: W = Wqf; b = bqf; C = g_wave;             break;
        case 1: W = Wkf; b = bkf; C = g_wave + SLICE;     break;
        case 2: W = Wqp; b = bqp; C = g_wave + 2 * SLICE; break;
        case 3: W = Wkp; b = bkp; C = g_wave + 3 * SLICE; break;
        default: W = Wv; b = bv;  C = g_v;                break;
    }
    sgemm128(x, W, b, C, DMODEL, DMODEL);
}

// ---------------- final output GEMM: d_out = g_ao @ Wo + bo ----------------
__global__ __launch_bounds__(256) void out_gemm_kernel(const float* __restrict__ Wo,
                                                       const float* __restrict__ bo,
                                                       float* __restrict__ out)
{
    sgemm128(g_ao, Wo, bo, out, DMODEL, DMODEL);
}

// ---------------- wave normalization: w = sin(f*t + p); w /= max(||w||, eps) ----------------
// One warp per (qk, b, t, h) row; 2 elements per lane.
__global__ __launch_bounds__(256) void wave_kernel()
{
    int gid  = blockIdx.x * 8 + (threadIdx.x >> 5);   // 0 .. 131071
    int lane = threadIdx.x & 31;
    int qk = gid >> 16;          // 0 = q, 1 = k
    int r  = gid & 0xFFFF;       // b*T*H + t*H + h
    int h = r & 15;
    int t = (r >> 4) & 2047;
    int b = r >> 15;

    const float* fb = g_wave + (size_t)qk * SLICE;        // qf or kf
    const float* pb = g_wave + (size_t)(2 + qk) * SLICE;  // qp or kp
    size_t base = ((size_t)(b * T_SEQ + t)) * DMODEL + h * NWAVE;
    float tf = (float)t;

    float f0 = fb[base + lane],      f1 = fb[base + lane + 32];
    float p0 = pb[base + lane],      p1 = pb[base + lane + 32];
    // match JAX: round(f*t) then round(+p) — forbid FMA contraction here
    float w0 = sinf(__fadd_rn(__fmul_rn(f0, tf), p0));
    float w1 = sinf(__fadd_rn(__fmul_rn(f1, tf), p1));

    float s = w0 * w0 + w1 * w1;
#pragma unroll
    for (int o = 16; o > 0; o >>= 1) s += __shfl_xor_sync(0xffffffffu, s, o);
    float inv = 1.f / fmaxf(sqrtf(s), 1e-12f);

    float* dst = qk ? g_kn : g_qn;
    size_t ob = ((size_t)((b * HEADS + h) * T_SEQ + t)) * NWAVE;
    dst[ob + lane]      = w0 * inv;
    dst[ob + lane + 32] = w1 * inv;
}

// ---------------- pass 1: per-chunk KV sums M_c = kn_c^T @ v_c  (64x64, K=64) ----------------
__global__ __launch_bounds__(256) void kvchunk_kernel()
{
    int c = blockIdx.x, bh = blockIdx.y;
    int b = bh >> 4, h = bh & 15;
    __shared__ float ks[CHUNK * NWAVE];
    __shared__ float vs[CHUNK * HDIM];
    const float* knp = g_kn + ((size_t)bh * T_SEQ + c * CHUNK) * NWAVE;
    const float* vp  = g_v + ((size_t)(b * T_SEQ + c * CHUNK)) * DMODEL + h * HDIM;
    for (int idx = threadIdx.x; idx < CHUNK * NWAVE; idx += 256) {
        ks[idx] = knp[idx];                       // [s][w]
        int s = idx >> 6, d = idx & 63;
        vs[idx] = vp[(size_t)s * DMODEL + d];     // [s][d]
    }
    __syncthreads();
    int tw = (threadIdx.x >> 4) * 4, td = (threadIdx.x & 15) * 4;
    float acc[4][4] = {};
    for (int s = 0; s < CHUNK; s++) {
        float kr[4], vr[4];
#pragma unroll
        for (int i = 0; i < 4; i++) kr[i] = ks[s * NWAVE + tw + i];
#pragma unroll
        for (int j = 0; j < 4; j++) vr[j] = vs[s * HDIM + td + j];
#pragma unroll
        for (int i = 0; i < 4; i++)
#pragma unroll
            for (int j = 0; j < 4; j++)
                acc[i][j] = fmaf(kr[i], vr[j], acc[i][j]);
    }
    float* Mp = g_M + ((size_t)bh * NCHUNK + c) * (NWAVE * HDIM);
#pragma unroll
    for (int i = 0; i < 4; i++)
#pragma unroll
        for (int j = 0; j < 4; j++)
            Mp[(tw + i) * HDIM + td + j] = acc[i][j];
}

// ---------------- pass 2: exclusive prefix sum over chunks per (bh, element) ----------------
__global__ __launch_bounds__(256) void prefix_kernel()
{
    int bh = blockIdx.y;
    int e = blockIdx.x * 256 + threadIdx.x;   // 0..4095
    size_t base = (size_t)bh * NCHUNK * (NWAVE * HDIM) + e;
    float run = 0.f;
#pragma unroll
    for (int c = 0; c < NCHUNK; c++) {
        g_S[base + (size_t)c * (NWAVE * HDIM)] = run;
        run += g_M[base + (size_t)c * (NWAVE * HDIM)];
    }
}

// ---------------- pass 3: per-chunk output ----------------
// out_c = (causal(qn_c @ kn_c^T) @ v_c + qn_c @ S_c) * scale[h] / sqrt(t+1)
__global__ __launch_bounds__(256) void attnout_kernel(const float* __restrict__ scale)
{
    int c = blockIdx.x, bh = blockIdx.y;
    int b = bh >> 4, h = bh & 15;
    int t0 = c * CHUNK;
    __shared__ float Xs[NWAVE * CHUNK];   // qT: [w][t]
    __shared__ float Ys[NWAVE * CHUNK];   // kT, then v, then S
    __shared__ float Zs[CHUNK * CHUNK];   // intra-chunk attn [t][s]

    const float* qp_ = g_qn + ((size_t)bh * T_SEQ + t0) * NWAVE;
    const float* kp_ = g_kn + ((size_t)bh * T_SEQ + t0) * NWAVE;
    for (int idx = threadIdx.x; idx < CHUNK * NWAVE; idx += 256) {
        int t = idx >> 6, w = idx & 63;
        Xs[w * CHUNK + t] = qp_[idx];
        Ys[w * CHUNK + t] = kp_[idx];
    }
    __syncthreads();

    int ty = threadIdx.x >> 4, tx = threadIdx.x & 15;
    int tr = ty * 4, sc = tx * 4;

    // intra-chunk attn = qn @ kn^T with causal mask (local s <= local t)
    {
        float acc[4][4] = {};
        for (int w = 0; w < NWAVE; w++) {
            float qr[4], kr[4];
#pragma unroll
            for (int i = 0; i < 4; i++) qr[i] = Xs[w * CHUNK + tr + i];
#pragma unroll
            for (int j = 0; j < 4; j++) kr[j] = Ys[w * CHUNK + sc + j];
#pragma unroll
            for (int i = 0; i < 4; i++)
#pragma unroll
                for (int j = 0; j < 4; j++)
                    acc[i][j] = fmaf(qr[i], kr[j], acc[i][j]);
        }
#pragma unroll
        for (int i = 0; i < 4; i++)
#pragma unroll
            for (int j = 0; j < 4; j++)
                Zs[(tr + i) * CHUNK + sc + j] = (sc + j <= tr + i) ? acc[i][j] : 0.f;
    }
    __syncthreads();

    // load v chunk into Ys
    const float* vp = g_v + ((size_t)(b * T_SEQ + t0)) * DMODEL + h * HDIM;
    for (int idx = threadIdx.x; idx < CHUNK * HDIM; idx += 256) {
        int s = idx >> 6, d = idx & 63;
        Ys[idx] = vp[(size_t)s * DMODEL + d];
    }
    __syncthreads();

    float out[4][4] = {};
    // intra-chunk: attn @ v
    for (int s = 0; s < CHUNK; s++) {
        float ar[4], vr[4];
#pragma unroll
        for (int i = 0; i < 4; i++) ar[i] = Zs[(tr + i) * CHUNK + s];
#pragma unroll
        for (int j = 0; j < 4; j++) vr[j] = Ys[s * HDIM + sc + j];
#pragma unroll
        for (int i = 0; i < 4; i++)
#pragma unroll
            for (int j = 0; j < 4; j++)
                out[i][j] = fmaf(ar[i], vr[j], out[i][j]);
    }
    __syncthreads();

    // load prefix state S into Ys
    const float* Sp = g_S + ((size_t)bh * NCHUNK + c) * (NWAVE * HDIM);
    for (int idx = threadIdx.x; idx < NWAVE * HDIM; idx += 256) Ys[idx] = Sp[idx];
    __syncthreads();

    // cross-chunk: qn @ S
    for (int w = 0; w < NWAVE; w++) {
        float qr[4], sr[4];
#pragma unroll
        for (int i = 0; i < 4; i++) qr[i] = Xs[w * CHUNK + tr + i];
#pragma unroll
        for (int j = 0; j < 4; j++) sr[j] = Ys[w * HDIM + sc + j];
#pragma unroll
        for (int i = 0; i < 4; i++)
#pragma unroll
            for (int j = 0; j < 4; j++)
                out[i][j] = fmaf(qr[i], sr[j], out[i][j]);
    }

    float sch = scale[h];
    float* op = g_ao + ((size_t)(b * T_SEQ + t0)) * DMODEL + h * HDIM;
#pragma unroll
    for (int i = 0; i < 4; i++) {
        float fac = sch / sqrtf((float)(t0 + tr + i + 1));
        float4 o;
        o.x = out[i][0] * fac;
        o.y = out[i][1] * fac;
        o.z = out[i][2] * fac;
        o.w = out[i][3] * fac;
        *(float4*)(op + (size_t)(tr + i) * DMODEL + sc) = o;
    }
}

// ---------------- launch ----------------
extern "C" void kernel_launch(void* const* d_in, const int* in_sizes, int n_in,
                              void* d_out, int out_size)
{
    const float* x   = (const float*)d_in[0];
    const float* Wqf = (const float*)d_in[1];
    const float* bqf = (const float*)d_in[2];
    const float* Wkf = (const float*)d_in[3];
    const float* bkf = (const float*)d_in[4];
    const float* Wqp = (const float*)d_in[5];
    const float* bqp = (const float*)d_in[6];
    const float* Wkp = (const float*)d_in[7];
    const float* bkp = (const float*)d_in[8];
    const float* Wv  = (const float*)d_in[9];
    const float* bv  = (const float*)d_in[10];
    const float* Wo  = (const float*)d_in[11];
    const float* bo  = (const float*)d_in[12];
    const float* scl = (const float*)d_in[13];

    proj_kernel<<<dim3(DMODEL / 128, ROWS / 128, 5), 256>>>(
        x, Wqf, bqf, Wkf, bkf, Wqp, bqp, Wkp, bkp, Wv, bv);
    wave_kernel<<<(2 * BATCH * T_SEQ * HEADS) / 8, 256>>>();
    kvchunk_kernel<<<dim3(NCHUNK, BH), 256>>>();
    prefix_kernel<<<dim3(16, BH), 256>>>();
    attnout_kernel<<<dim3(NCHUNK, BH), 256>>>(scl);
    out_gemm_kernel<<<dim3(DMODEL / 128, ROWS / 128), 256>>>(Wo, bo, (float*)d_out);
}

// round 2
// speedup vs baseline: 1.0765x; 1.0765x over previous
#include <cuda_runtime.h>
#include <math.h>

// Problem constants
#define T_SEQ 2048
#define BATCH 2
#define DMODEL 1024
#define HEADS 16
#define NWAVE 64
#define HDIM 64
#define ROWS (BATCH * T_SEQ)            // 4096
#define SLICE ((size_t)ROWS * DMODEL)   // 4194304 elements
#define BH (BATCH * HEADS)              // 32
#define CHUNK 64
#define NCHUNK (T_SEQ / CHUNK)          // 32

// ---------------- device scratch (no allocations allowed) ----------------
__device__ float g_wave[4 * SLICE];              // qf, kf, qp, kp raw projections
__device__ float g_v[SLICE];                     // v projection [b,t,h*64+d]
__device__ float g_qn[(size_t)BH * T_SEQ * NWAVE];  // normalized q waves [bh][t][w]
__device__ float g_kn[(size_t)BH * T_SEQ * NWAVE];  // normalized k waves [bh][t][w]
__device__ float g_M[(size_t)BH * NCHUNK * NWAVE * HDIM];  // per-chunk kn^T v
__device__ float g_S[(size_t)BH * NCHUNK * NWAVE * HDIM];  // exclusive prefix states
__device__ float g_ao[SLICE];                    // attention output [b,t,h*64+d]

// ---------------- packed f32x2 helpers (Blackwell FFMA2) ----------------
__device__ __forceinline__ void ffma2(unsigned long long& d,
                                      unsigned long long a,
                                      unsigned long long b)
{
    asm("fma.rn.f32x2 %0, %1, %2, %0;" : "+l"(d) : "l"(a), "l"(b));
}
__device__ __forceinline__ unsigned long long pack2(float x)
{
    unsigned long long r;
    asm("mov.b64 %0, {%1, %1};" : "=l"(r) : "f"(x));
    return r;
}
__device__ __forceinline__ float2 unpack2(unsigned long long v)
{
    float2 r;
    asm("mov.b64 {%0, %1}, %2;" : "=f"(r.x), "=f"(r.y) : "l"(v));
    return r;
}

// ---------------- 128x128 FFMA2 register-tiled SGEMM (C = A*B + bias) ----------------
// A [M,K] row-major, B [K,N] row-major. 256 threads.
// Thread tile: 4 rows x 16 cols; cols are 4 groups of 4 at stride 32
// (conflict-free LDS.128 from Bs). K tile = 16 with register prefetch.
__device__ __forceinline__ void sgemm128(const float* __restrict__ A,
                                         const float* __restrict__ Bw,
                                         const float* __restrict__ bias,
                                         float* __restrict__ C,
                                         int N, int K)
{
    __shared__ float As[16][128];   // As[k][m]
    __shared__ float Bs[16][128];   // Bs[k][n]
    const int tid  = threadIdx.x;
    const int row0 = blockIdx.y * 128;
    const int col0 = blockIdx.x * 128;
    const int arow = tid >> 1, acol = (tid & 1) * 8;     // A tile: 128 rows x 16 k
    const int brow = tid >> 4, bcol = (tid & 15) * 4;    // B tile: 16 k x 128 n
    const int ty = tid >> 3;        // 0..31 -> 4 rows each
    const int tx = tid & 7;         // 0..7  -> 4 col-groups of 4, stride 32

    unsigned long long acc[4][8];   // [row][col-pair]; pair jj: group jj>>1, sub (jj&1)*2
#pragma unroll
    for (int i = 0; i < 4; i++)
#pragma unroll
        for (int j = 0; j < 8; j++) acc[i][j] = 0ULL;

    const float* aptr = A + (size_t)(row0 + arow) * K + acol;
    const float* bptr = Bw + (size_t)brow * N + col0 + bcol;

    float4 pa0 = *(const float4*)(aptr);
    float4 pa1 = *(const float4*)(aptr + 4);
    float4 pb0 = *(const float4*)(bptr);
    float4 pb1 = *(const float4*)(bptr + 64);

    for (int kk = 0; kk < K; kk += 16) {
        // store current tile to shared
        As[acol + 0][arow] = pa0.x;
        As[acol + 1][arow] = pa0.y;
        As[acol + 2][arow] = pa0.z;
        As[acol + 3][arow] = pa0.w;
        As[acol + 4][arow] = pa1.x;
        As[acol + 5][arow] = pa1.y;
        As[acol + 6][arow] = pa1.z;
        As[acol + 7][arow] = pa1.w;
        *(float4*)(&Bs[brow][bcol])      = pb0;
        *(float4*)(&Bs[brow][bcol + 64]) = pb1;
        __syncthreads();

        // prefetch next tile while computing
        if (kk + 16 < K) {
            pa0 = *(const float4*)(aptr + kk + 16);
            pa1 = *(const float4*)(aptr + kk + 20);
            const float* bn = bptr + (size_t)(kk + 16) * N;
            pb0 = *(const float4*)(bn);
            pb1 = *(const float4*)(bn + 64);
        }

#pragma unroll
        for (int k = 0; k < 16; k++) {
            float4 av = *(const float4*)(&As[k][ty * 4]);
            unsigned long long ap2[4];
            ap2[0] = pack2(av.x);
            ap2[1] = pack2(av.y);
            ap2[2] = pack2(av.z);
            ap2[3] = pack2(av.w);
            ulonglong2 b0 = *(const ulonglong2*)(&Bs[k][tx * 4]);
            ulonglong2 b1 = *(const ulonglong2*)(&Bs[k][tx * 4 + 32]);
            ulonglong2 b2 = *(const ulonglong2*)(&Bs[k][tx * 4 + 64]);
            ulonglong2 b3 = *(const ulonglong2*)(&Bs[k][tx * 4 + 96]);
            unsigned long long bv[8] = {b0.x, b0.y, b1.x, b1.y,
                                        b2.x, b2.y, b3.x, b3.y};
#pragma unroll
            for (int i = 0; i < 4; i++)
#pragma unroll
                for (int j = 0; j < 8; j++)
                    ffma2(acc[i][j], ap2[i], bv[j]);
        }
        __syncthreads();
    }

    // epilogue: unpack, add bias, store
#pragma unroll
    for (int i = 0; i < 4; i++) {
        int r = row0 + ty * 4 + i;
#pragma unroll
        for (int q = 0; q < 4; q++) {
            int c = col0 + q * 32 + tx * 4;
            float2 lo = unpack2(acc[i][2 * q]);
            float2 hi = unpack2(acc[i][2 * q + 1]);
            float4 bb = *(const float4*)(bias + c);
            float4 o;
            o.x = lo.x + bb.x;
            o.y = lo.y + bb.y;
            o.z = hi.x + bb.z;
            o.w = hi.y + bb.w;
            *(float4*)(C + (size_t)r * N + c) = o;
        }
    }
}

// ---------------- projection kernel: 5 GEMMs via blockIdx.z ----------------
__global__ __launch_bounds__(256) void proj_kernel(
    const float* __restrict__ x,
    const float* __restrict__ Wqf, const float* __restrict__ bqf,
    const float* __restrict__ Wkf, const float* __restrict__ bkf,
    const float* __restrict__ Wqp, const float* __restrict__ bqp,
    const float* __restrict__ Wkp, const float* __restrict__ bkp,
    const float* __restrict__ Wv,  const float* __restrict__ bv)
{
    const float* W;
    const float* b;
    float* C;
    switch (blockIdx.z) {
        case 0: W = Wqf; b = bqf; C = g_wave;             break;
        case 1: W = Wkf; b = bkf; C = g_wave + SLICE;     break;
        case 2: W = Wqp; b = bqp; C = g_wave + 2 * SLICE; break;
        case 3: W = Wkp; b = bkp; C = g_wave + 3 * SLICE; break;
        default: W = Wv; b = bv;  C = g_v;                break;
    }
    sgemm128(x, W, b, C, DMODEL, DMODEL);
}

// ---------------- final output GEMM: d_out = g_ao @ Wo + bo ----------------
__global__ __launch_bounds__(256) void out_gemm_kernel(const float* __restrict__ Wo,
                                                       const float* __restrict__ bo,
                                                       float* __restrict__ out)
{
    sgemm128(g_ao, Wo, bo, out, DMODEL, DMODEL);
}

// ---------------- wave normalization: w = sin(f*t + p); w /= max(||w||, eps) ----------------
// One warp per (qk, b, t, h) row; 2 elements per lane.
__global__ __launch_bounds__(256) void wave_kernel()
{
    int gid  = blockIdx.x * 8 + (threadIdx.x >> 5);   // 0 .. 131071
    int lane = threadIdx.x & 31;
    int qk = gid >> 16;          // 0 = q, 1 = k
    int r  = gid & 0xFFFF;       // b*T*H + t*H + h
    int h = r & 15;
    int t = (r >> 4) & 2047;
    int b = r >> 15;

    const float* fb = g_wave + (size_t)qk * SLICE;        // qf or kf
    const float* pb = g_wave + (size_t)(2 + qk) * SLICE;  // qp or kp
    size_t base = ((size_t)(b * T_SEQ + t)) * DMODEL + h * NWAVE;
    float tf = (float)t;

    float f0 = fb[base + lane],      f1 = fb[base + lane + 32];
    float p0 = pb[base + lane],      p1 = pb[base + lane + 32];
    // match JAX: round(f*t) then round(+p) — forbid FMA contraction here
    float w0 = sinf(__fadd_rn(__fmul_rn(f0, tf), p0));
    float w1 = sinf(__fadd_rn(__fmul_rn(f1, tf), p1));

    float s = w0 * w0 + w1 * w1;
#pragma unroll
    for (int o = 16; o > 0; o >>= 1) s += __shfl_xor_sync(0xffffffffu, s, o);
    float inv = 1.f / fmaxf(sqrtf(s), 1e-12f);

    float* dst = qk ? g_kn : g_qn;
    size_t ob = ((size_t)((b * HEADS + h) * T_SEQ + t)) * NWAVE;
    dst[ob + lane]      = w0 * inv;
    dst[ob + lane + 32] = w1 * inv;
}

// ---------------- pass 1: per-chunk KV sums M_c = kn_c^T @ v_c  (64x64, K=64) ----------------
__global__ __launch_bounds__(256) void kvchunk_kernel()
{
    int c = blockIdx.x, bh = blockIdx.y;
    int b = bh >> 4, h = bh & 15;
    __shared__ float ks[CHUNK * NWAVE];
    __shared__ float vs[CHUNK * HDIM];
    const float* knp = g_kn + ((size_t)bh * T_SEQ + c * CHUNK) * NWAVE;
    const float* vp  = g_v + ((size_t)(b * T_SEQ + c * CHUNK)) * DMODEL + h * HDIM;
    for (int idx = threadIdx.x; idx < CHUNK * NWAVE; idx += 256) {
        ks[idx] = knp[idx];                       // [s][w]
        int s = idx >> 6, d = idx & 63;
        vs[idx] = vp[(size_t)s * DMODEL + d];     // [s][d]
    }
    __syncthreads();
    int tw = (threadIdx.x >> 4) * 4, td = (threadIdx.x & 15) * 4;
    float acc[4][4] = {};
    for (int s = 0; s < CHUNK; s++) {
        float kr[4], vr[4];
#pragma unroll
        for (int i = 0; i < 4; i++) kr[i] = ks[s * NWAVE + tw + i];
#pragma unroll
        for (int j = 0; j < 4; j++) vr[j] = vs[s * HDIM + td + j];
#pragma unroll
        for (int i = 0; i < 4; i++)
#pragma unroll
            for (int j = 0; j < 4; j++)
                acc[i][j] = fmaf(kr[i], vr[j], acc[i][j]);
    }
    float* Mp = g_M + ((size_t)bh * NCHUNK + c) * (NWAVE * HDIM);
#pragma unroll
    for (int i = 0; i < 4; i++)
#pragma unroll
        for (int j = 0; j < 4; j++)
            Mp[(tw + i) * HDIM + td + j] = acc[i][j];
}

// ---------------- pass 2: exclusive prefix sum over chunks per (bh, element) ----------------
__global__ __launch_bounds__(256) void prefix_kernel()
{
    int bh = blockIdx.y;
    int e = blockIdx.x * 256 + threadIdx.x;   // 0..4095
    size_t base = (size_t)bh * NCHUNK * (NWAVE * HDIM) + e;
    float run = 0.f;
#pragma unroll
    for (int c = 0; c < NCHUNK; c++) {
        g_S[base + (size_t)c * (NWAVE * HDIM)] = run;
        run += g_M[base + (size_t)c * (NWAVE * HDIM)];
    }
}

// ---------------- pass 3: per-chunk output ----------------
// out_c = (causal(qn_c @ kn_c^T) @ v_c + qn_c @ S_c) * scale[h] / sqrt(t+1)
__global__ __launch_bounds__(256) void attnout_kernel(const float* __restrict__ scale)
{
    int c = blockIdx.x, bh = blockIdx.y;
    int b = bh >> 4, h = bh & 15;
    int t0 = c * CHUNK;
    __shared__ float Xs[NWAVE * CHUNK];   // qT: [w][t]
    __shared__ float Ys[NWAVE * CHUNK];   // kT, then v, then S
    __shared__ float Zs[CHUNK * CHUNK];   // intra-chunk attn [t][s]

    const float* qp_ = g_qn + ((size_t)bh * T_SEQ + t0) * NWAVE;
    const float* kp_ = g_kn + ((size_t)bh * T_SEQ + t0) * NWAVE;
    for (int idx = threadIdx.x; idx < CHUNK * NWAVE; idx += 256) {
        int t = idx >> 6, w = idx & 63;
        Xs[w * CHUNK + t] = qp_[idx];
        Ys[w * CHUNK + t] = kp_[idx];
    }
    __syncthreads();

    int ty = threadIdx.x >> 4, tx = threadIdx.x & 15;
    int tr = ty * 4, sc = tx * 4;

    // intra-chunk attn = qn @ kn^T with causal mask (local s <= local t)
    {
        float acc[4][4] = {};
        for (int w = 0; w < NWAVE; w++) {
            float qr[4], kr[4];
#pragma unroll
            for (int i = 0; i < 4; i++) qr[i] = Xs[w * CHUNK + tr + i];
#pragma unroll
            for (int j = 0; j < 4; j++) kr[j] = Ys[w * CHUNK + sc + j];
#pragma unroll
            for (int i = 0; i < 4; i++)
#pragma unroll
                for (int j = 0; j < 4; j++)
                    acc[i][j] = fmaf(qr[i], kr[j], acc[i][j]);
        }
#pragma unroll
        for (int i = 0; i < 4; i++)
#pragma unroll
            for (int j = 0; j < 4; j++)
                Zs[(tr + i) * CHUNK + sc + j] = (sc + j <= tr + i) ? acc[i][j] : 0.f;
    }
    __syncthreads();

    // load v chunk into Ys
    const float* vp = g_v + ((size_t)(b * T_SEQ + t0)) * DMODEL + h * HDIM;
    for (int idx = threadIdx.x; idx < CHUNK * HDIM; idx += 256) {
        int s = idx >> 6, d = idx & 63;
        Ys[idx] = vp[(size_t)s * DMODEL + d];
    }
    __syncthreads();

    float out[4][4] = {};
    // intra-chunk: attn @ v
    for (int s = 0; s < CHUNK; s++) {
        float ar[4], vr[4];
#pragma unroll
        for (int i = 0; i < 4; i++) ar[i] = Zs[(tr + i) * CHUNK + s];
#pragma unroll
        for (int j = 0; j < 4; j++) vr[j] = Ys[s * HDIM + sc + j];
#pragma unroll
        for (int i = 0; i < 4; i++)
#pragma unroll
            for (int j = 0; j < 4; j++)
                out[i][j] = fmaf(ar[i], vr[j], out[i][j]);
    }
    __syncthreads();

    // load prefix state S into Ys
    const float* Sp = g_S + ((size_t)bh * NCHUNK + c) * (NWAVE * HDIM);
    for (int idx = threadIdx.x; idx < NWAVE * HDIM; idx += 256) Ys[idx] = Sp[idx];
    __syncthreads();

    // cross-chunk: qn @ S
    for (int w = 0; w < NWAVE; w++) {
        float qr[4], sr[4];
#pragma unroll
        for (int i = 0; i < 4; i++) qr[i] = Xs[w * CHUNK + tr + i];
#pragma unroll
        for (int j = 0; j < 4; j++) sr[j] = Ys[w * HDIM + sc + j];
#pragma unroll
        for (int i = 0; i < 4; i++)
#pragma unroll
            for (int j = 0; j < 4; j++)
                out[i][j] = fmaf(qr[i], sr[j], out[i][j]);
    }

    float sch = scale[h];
    float* op = g_ao + ((size_t)(b * T_SEQ + t0)) * DMODEL + h * HDIM;
#pragma unroll
    for (int i = 0; i < 4; i++) {
        float fac = sch / sqrtf((float)(t0 + tr + i + 1));
        float4 o;
        o.x = out[i][0] * fac;
        o.y = out[i][1] * fac;
        o.z = out[i][2] * fac;
        o.w = out[i][3] * fac;
        *(float4*)(op + (size_t)(tr + i) * DMODEL + sc) = o;
    }
}

// ---------------- launch ----------------
extern "C" void kernel_launch(void* const* d_in, const int* in_sizes, int n_in,
                              void* d_out, int out_size)
{
    const float* x   = (const float*)d_in[0];
    const float* Wqf = (const float*)d_in[1];
    const float* bqf = (const float*)d_in[2];
    const float* Wkf = (const float*)d_in[3];
    const float* bkf = (const float*)d_in[4];
    const float* Wqp = (const float*)d_in[5];
    const float* bqp = (const float*)d_in[6];
    const float* Wkp = (const float*)d_in[7];
    const float* bkp = (const float*)d_in[8];
    const float* Wv  = (const float*)d_in[9];
    const float* bv  = (const float*)d_in[10];
    const float* Wo  = (const float*)d_in[11];
    const float* bo  = (const float*)d_in[12];
    const float* scl = (const float*)d_in[13];

    proj_kernel<<<dim3(DMODEL / 128, ROWS / 128, 5), 256>>>(
        x, Wqf, bqf, Wkf, bkf, Wqp, bqp, Wkp, bkp, Wv, bv);
    wave_kernel<<<(2 * BATCH * T_SEQ * HEADS) / 8, 256>>>();
    kvchunk_kernel<<<dim3(NCHUNK, BH), 256>>>();
    prefix_kernel<<<dim3(16, BH), 256>>>();
    attnout_kernel<<<dim3(NCHUNK, BH), 256>>>(scl);
    out_gemm_kernel<<<dim3(DMODEL / 128, ROWS / 128), 256>>>(Wo, bo, (float*)d_out);
}